// round 2
// baseline (speedup 1.0000x reference)
#include <cuda_runtime.h>

#define DIMC   256
#define NHEADS 8
#define HDIM   32
#define MAXN   10048

// Scratch (no cudaMalloc allowed) — ~41 MB of __device__ globals.
__device__ float g_q[MAXN * DIMC];
__device__ float g_k[MAXN * DIMC];
__device__ float g_v[MAXN * DIMC];
__device__ float g_acc[MAXN * DIMC];

// ---------------------------------------------------------------------------
// Zero the accumulator (must happen every launch; d_out is poisoned, g_acc is
// stale from the previous replay).
// ---------------------------------------------------------------------------
__global__ void __launch_bounds__(256) zero_acc_kernel(int n4) {
    int i = blockIdx.x * blockDim.x + threadIdx.x;
    float4 z = make_float4(0.f, 0.f, 0.f, 0.f);
    int stride = gridDim.x * blockDim.x;
    for (; i < n4; i += stride)
        reinterpret_cast<float4*>(g_acc)[i] = z;
}

// ---------------------------------------------------------------------------
// Tiled fp32 GEMM:  C[m][n] = sum_k X[m][k] * W[n][k] + bias[n]
// (nn.Linear: y = x @ W^T + b; both X and W are K-major row-major.)
// BM=BN=64, BK=16, 256 threads, 4x4 outputs per thread.
// ---------------------------------------------------------------------------
__device__ __forceinline__ void gemm_tile(
    const float* __restrict__ X, int M,
    const float* __restrict__ W,
    const float* __restrict__ Bv,
    float* __restrict__ C,
    int m0, int n0)
{
    __shared__ float As[16][64];
    __shared__ float Bs[16][64];

    int tid = threadIdx.x;
    int tr = tid >> 4;          // 0..15 (output row group)
    int tc = tid & 15;          // 0..15 (output col group)
    int lr = tid >> 2;          // 0..63 (load row)
    int lk = (tid & 3) << 2;    // 0,4,8,12 (load k offset)

    float acc[16];
#pragma unroll
    for (int i = 0; i < 16; i++) acc[i] = 0.f;

    bool avalid = (m0 + lr) < M;
    const float* Arow = X + (size_t)(m0 + lr) * DIMC + lk;
    const float* Brow = W + (size_t)(n0 + lr) * DIMC + lk;

    for (int k0 = 0; k0 < DIMC; k0 += 16) {
        float4 a = avalid ? *reinterpret_cast<const float4*>(Arow + k0)
                          : make_float4(0.f, 0.f, 0.f, 0.f);
        float4 b = *reinterpret_cast<const float4*>(Brow + k0);
        As[lk + 0][lr] = a.x; As[lk + 1][lr] = a.y;
        As[lk + 2][lr] = a.z; As[lk + 3][lr] = a.w;
        Bs[lk + 0][lr] = b.x; Bs[lk + 1][lr] = b.y;
        Bs[lk + 2][lr] = b.z; Bs[lk + 3][lr] = b.w;
        __syncthreads();

#pragma unroll
        for (int kk = 0; kk < 16; kk++) {
            float4 ta = *reinterpret_cast<const float4*>(&As[kk][tr << 2]);
            float4 tb = *reinterpret_cast<const float4*>(&Bs[kk][tc << 2]);
            float ar[4] = {ta.x, ta.y, ta.z, ta.w};
            float br[4] = {tb.x, tb.y, tb.z, tb.w};
#pragma unroll
            for (int i = 0; i < 4; i++)
#pragma unroll
                for (int j = 0; j < 4; j++)
                    acc[i * 4 + j] = fmaf(ar[i], br[j], acc[i * 4 + j]);
        }
        __syncthreads();
    }

    float4 bb = *reinterpret_cast<const float4*>(Bv + n0 + (tc << 2));
#pragma unroll
    for (int i = 0; i < 4; i++) {
        int gm = m0 + (tr << 2) + i;
        if (gm < M) {
            float4 o = make_float4(acc[i * 4 + 0] + bb.x,
                                   acc[i * 4 + 1] + bb.y,
                                   acc[i * 4 + 2] + bb.z,
                                   acc[i * 4 + 3] + bb.w);
            *reinterpret_cast<float4*>(C + (size_t)gm * DIMC + n0 + (tc << 2)) = o;
        }
    }
}

// QKV projections: blockIdx.z selects Q/K/V; outputs go to __device__ scratch.
__global__ void __launch_bounds__(256) gemm_qkv_kernel(
    const float* __restrict__ X, int M,
    const float* __restrict__ Wq, const float* __restrict__ bq,
    const float* __restrict__ Wk, const float* __restrict__ bk,
    const float* __restrict__ Wv, const float* __restrict__ bv)
{
    const float* W; const float* B; float* C;
    int z = blockIdx.z;
    if (z == 0)      { W = Wq; B = bq; C = g_q; }
    else if (z == 1) { W = Wk; B = bk; C = g_k; }
    else             { W = Wv; B = bv; C = g_v; }
    gemm_tile(X, M, W, B, C, blockIdx.y * 64, blockIdx.x * 64);
}

// Output projection: reads g_acc, writes d_out.
__global__ void __launch_bounds__(256) gemm_out_kernel(
    int M, const float* __restrict__ Wo, const float* __restrict__ bo,
    float* __restrict__ out)
{
    gemm_tile(g_acc, M, Wo, bo, out, blockIdx.y * 64, blockIdx.x * 64);
}

// ---------------------------------------------------------------------------
// Edge kernel: one warp per edge.
// Lane l owns elements [4l, 4l+4) (head l/8) and [4(l+32), 4(l+32)+4)
// (head l/8 + 4) of the 256-wide row. Per-head dot via xor-shuffle reduction
// over each aligned 8-lane group; softmax over the 8 heads; scatter with
// red.global.add.v4.f32.
// ---------------------------------------------------------------------------
__device__ __forceinline__ void red_add_v4(float* addr, float4 v) {
    asm volatile("red.global.add.v4.f32 [%0], {%1, %2, %3, %4};"
                 :: "l"(addr), "f"(v.x), "f"(v.y), "f"(v.z), "f"(v.w)
                 : "memory");
}

__global__ void __launch_bounds__(256) edge_kernel(
    const int* __restrict__ src, const int* __restrict__ dst, int E)
{
    int e = (blockIdx.x << 3) + (threadIdx.x >> 5);
    if (e >= E) return;
    int lane = threadIdx.x & 31;

    int s = src[e];
    int d = dst[e];

    const float4* qp = reinterpret_cast<const float4*>(g_q + (size_t)s * DIMC);
    const float4* kp = reinterpret_cast<const float4*>(g_k + (size_t)d * DIMC);

    float4 a0 = qp[lane];
    float4 a1 = qp[lane + 32];
    float4 b0 = kp[lane];
    float4 b1 = kp[lane + 32];

    float p0 = a0.x * b0.x + a0.y * b0.y + a0.z * b0.z + a0.w * b0.w;
    float p1 = a1.x * b1.x + a1.y * b1.y + a1.z * b1.z + a1.w * b1.w;

    // Reduce within each aligned 8-lane head group.
#pragma unroll
    for (int m = 1; m <= 4; m <<= 1) {
        p0 += __shfl_xor_sync(0xffffffffu, p0, m);
        p1 += __shfl_xor_sync(0xffffffffu, p1, m);
    }

    const float scale = 0.17677669529663687f;   // 1/sqrt(32)
    float sc0 = p0 * scale;   // score for head lane/8
    float sc1 = p1 * scale;   // score for head lane/8 + 4

    // Gather all 8 head scores (heads 0..3 from p0 of lanes 0,8,16,24;
    // heads 4..7 from p1 of the same lanes).
    float sh[8];
#pragma unroll
    for (int h = 0; h < 4; h++) {
        sh[h]     = __shfl_sync(0xffffffffu, sc0, h << 3);
        sh[h + 4] = __shfl_sync(0xffffffffu, sc1, h << 3);
    }

    float mx = sh[0];
#pragma unroll
    for (int h = 1; h < 8; h++) mx = fmaxf(mx, sh[h]);
    float sum = 0.f;
#pragma unroll
    for (int h = 0; h < 8; h++) sum += expf(sh[h] - mx);
    float inv = 1.0f / sum;

    float w0 = expf(sc0 - mx) * inv;   // attn weight for head lane/8
    float w1 = expf(sc1 - mx) * inv;   // attn weight for head lane/8 + 4

    const float4* vp = reinterpret_cast<const float4*>(g_v + (size_t)s * DIMC);
    float4 v0 = vp[lane];
    float4 v1 = vp[lane + 32];

    float* op = g_acc + (size_t)d * DIMC;
    red_add_v4(op + (lane << 2),
               make_float4(v0.x * w0, v0.y * w0, v0.z * w0, v0.w * w0));
    red_add_v4(op + ((lane + 32) << 2),
               make_float4(v1.x * w1, v1.y * w1, v1.z * w1, v1.w * w1));
}

// ---------------------------------------------------------------------------
// Launch
// ---------------------------------------------------------------------------
extern "C" void kernel_launch(void* const* d_in, const int* in_sizes, int n_in,
                              void* d_out, int out_size)
{
    const float* x   = (const float*)d_in[0];
    const int*   src = (const int*)  d_in[1];
    const int*   dst = (const int*)  d_in[2];
    const float* Wq  = (const float*)d_in[3];
    const float* bq  = (const float*)d_in[4];
    const float* Wk  = (const float*)d_in[5];
    const float* bk  = (const float*)d_in[6];
    const float* Wv  = (const float*)d_in[7];
    const float* bv  = (const float*)d_in[8];
    const float* Wo  = (const float*)d_in[9];
    const float* bo  = (const float*)d_in[10];
    float* out = (float*)d_out;

    int N = in_sizes[0] / DIMC;
    int E = in_sizes[1];

    int mtiles = (N + 63) / 64;

    // 1) zero accumulator
    int n4 = (N * DIMC) / 4;
    zero_acc_kernel<<<(n4 + 255) / 256, 256>>>(n4);

    // 2) Q/K/V projections
    {
        dim3 grid(DIMC / 64, mtiles, 3);
        gemm_qkv_kernel<<<grid, 256>>>(x, N, Wq, bq, Wk, bk, Wv, bv);
    }

    // 3) per-edge attention + scatter
    edge_kernel<<<(E + 7) / 8, 256>>>(src, dst, E);

    // 4) output projection
    {
        dim3 grid(DIMC / 64, mtiles, 1);
        gemm_out_kernel<<<grid, 256>>>(N, Wo, bo, out);
    }
}